// round 2
// baseline (speedup 1.0000x reference)
#include <cuda_runtime.h>
#include <math_constants.h>

#define NP 128           // particles
#define NB 512           // batch
#define NH 512           // hidden
#define PB (NP*NB)       // 65536

// threefry key from jax.random.key(42): (k0=0, k1=42)
#define KS0 0u
#define KS1 42u
#define KS2 (KS0 ^ KS1 ^ 0x1BD11BDAu)

__device__ float d_LT[NB * NP];   // LT[b*128 + p] = log(0.5*exp(prob[p,b]) + 0.5/128)
__device__ int   d_idx[PB];       // indices[s*512 + b]

#define TFROUND(r) { x0 += x1; x1 = __funnelshift_l(x1, x1, (r)); x1 ^= x0; }

// jax partitionable threefry: one block per element i, counter (hi=0, lo=i),
// 32-bit output = lane0 ^ lane1.
__device__ __forceinline__ unsigned tf_bits(unsigned i) {
    unsigned x0 = KS0;        // counts_hi (=0) + ks0
    unsigned x1 = i + KS1;    // counts_lo + ks1
    TFROUND(13) TFROUND(15) TFROUND(26) TFROUND(6)
    x0 += KS1; x1 += KS2 + 1u;
    TFROUND(17) TFROUND(29) TFROUND(16) TFROUND(24)
    x0 += KS2; x1 += KS0 + 2u;
    TFROUND(13) TFROUND(15) TFROUND(26) TFROUND(6)
    x0 += KS0; x1 += KS1 + 3u;
    TFROUND(17) TFROUND(29) TFROUND(16) TFROUND(24)
    x0 += KS1; x1 += KS2 + 4u;
    TFROUND(13) TFROUND(15) TFROUND(26) TFROUND(6)
    x0 += KS2; x1 += KS0 + 5u;
    return x0 ^ x1;
}

__device__ __forceinline__ float gumbel_from_bits(unsigned bits) {
    // XLA uniform(minval=tiny, maxval=1): f in [0,1), u = max(tiny, f)
    unsigned fb = (bits >> 9) | 0x3f800000u;
    float f = __uint_as_float(fb) - 1.0f;
    float u = fmaxf(f, 1.17549435082228751e-38f);
    return -logf(-logf(u));
}

// K1: resampling logits, transposed for coalesced access in the sampler.
__global__ void logits_kernel(const float* __restrict__ prob) {
    int tid = blockIdx.x * blockDim.x + threadIdx.x;  // tid = b*128 + p
    if (tid >= NB * NP) return;
    int b = tid >> 7;
    int p = tid & 127;
    float pr = prob[p * NB + b];
    d_LT[tid] = logf(0.5f * expf(pr) + 0.00390625f);  // (1-alpha)/P = 0.5/128 exact
}

// K2: one warp per (s, b); lane covers p = lane + 32*j, j in [0,4).
__global__ void sample_kernel() {
    int gw = (blockIdx.x * blockDim.x + threadIdx.x) >> 5;   // 0..65535
    int lane = threadIdx.x & 31;
    if (gw >= NP * NB) return;
    int s = gw >> 9;        // 0..127
    int b = gw & 511;

    const float* lt = d_LT + b * NP;
    unsigned base = (unsigned)s * 65536u + (unsigned)b * 128u;

    float best = -CUDART_INF_F;
    int bp = 0;

    #pragma unroll
    for (int j = 0; j < 4; j++) {
        int p = lane + 32 * j;
        unsigned bits = tf_bits(base + (unsigned)p);
        float v = gumbel_from_bits(bits) + lt[p];
        if (v > best) { best = v; bp = p; }   // p increasing -> first-max kept
    }

    // warp argmax reduce, tie -> lower p (matches jnp.argmax first occurrence)
    #pragma unroll
    for (int off = 16; off > 0; off >>= 1) {
        float ov = __shfl_down_sync(0xffffffffu, best, off);
        int   op = __shfl_down_sync(0xffffffffu, bp, off);
        if (ov > best || (ov == best && op < bp)) { best = ov; bp = op; }
    }
    if (lane == 0) d_idx[s * NB + b] = bp;
}

// K3: reweight + per-batch-column logsumexp. One block per b, 128 threads (= s).
__global__ void probnew_kernel(const float* __restrict__ prob, float* __restrict__ out_prob) {
    int b = blockIdx.x;
    int s = threadIdx.x;
    int idx = d_idx[s * NB + b];
    float pg = prob[idx * NB + b];
    // match reference composition: w = exp(p); w = w/(a*w + c); lw = log(w)
    float w = expf(pg);
    float w2 = w / (0.5f * w + 0.00390625f);
    float lw = logf(w2);

    __shared__ float sh[NP];
    sh[s] = lw;
    __syncthreads();
    #pragma unroll
    for (int off = 64; off > 0; off >>= 1) {
        if (s < off) sh[s] = fmaxf(sh[s], sh[s + off]);
        __syncthreads();
    }
    float m = sh[0];
    __syncthreads();
    sh[s] = expf(lw - m);
    __syncthreads();
    #pragma unroll
    for (int off = 64; off > 0; off >>= 1) {
        if (s < off) sh[s] += sh[s + off];
        __syncthreads();
    }
    float lse = m + logf(sh[0]);
    out_prob[s * NB + b] = lw - lse;
}

// K4: row gather of particles. One block per output row, float4 copies.
__global__ void gather_kernel(const float* __restrict__ particles, float* __restrict__ out) {
    int r = blockIdx.x;            // r = s*512 + b
    int b = r & 511;
    int idx = d_idx[r];
    const float4* src = (const float4*)(particles + ((size_t)idx * NB + b) * (size_t)NH);
    float4* dst = (float4*)(out + (size_t)r * NH);
    dst[threadIdx.x] = src[threadIdx.x];
}

extern "C" void kernel_launch(void* const* d_in, const int* in_sizes, int n_in,
                              void* d_out, int out_size) {
    const float* particles = (const float*)d_in[0];   // [P*B, H]
    const float* prob      = (const float*)d_in[1];   // [P*B, 1]
    float* out = (float*)d_out;
    float* out_particles = out;                 // [P*B*H]
    float* out_prob = out + (size_t)PB * NH;    // [P*B]

    logits_kernel<<<(NB * NP + 255) / 256, 256>>>(prob);
    sample_kernel<<<(PB * 32 + 255) / 256, 256>>>();
    probnew_kernel<<<NB, NP>>>(prob, out_prob);
    gather_kernel<<<PB, NH / 4>>>(particles, out_particles);
}

// round 3
// speedup vs baseline: 1.6457x; 1.6457x over previous
#include <cuda_runtime.h>
#include <math_constants.h>

#define NP 128           // particles
#define NB 512           // batch
#define NH 512           // hidden
#define PB (NP*NB)       // 65536

// threefry key from jax.random.key(42): (k0=0, k1=42)
#define KS0 0u
#define KS1 42u
#define KS2 (KS0 ^ KS1 ^ 0x1BD11BDAu)

__device__ float d_LT[NB * NP];   // LT[b*128 + p] = log(0.5*exp(prob[p,b]) + 0.5/128)
__device__ int   d_idx[PB];       // indices[s*512 + b]

#define TFROUND(r) { x0 += x1; x1 = __funnelshift_l(x1, x1, (r)); x1 ^= x0; }

// jax partitionable threefry: one block per element i, counter (hi=0, lo=i),
// 32-bit output = lane0 ^ lane1.  (identical to passing round-2 version)
__device__ __forceinline__ unsigned tf_bits(unsigned i) {
    unsigned x0 = KS0;        // counts_hi (=0) + ks0
    unsigned x1 = i + KS1;    // counts_lo + ks1
    TFROUND(13) TFROUND(15) TFROUND(26) TFROUND(6)
    x0 += KS1; x1 += KS2 + 1u;
    TFROUND(17) TFROUND(29) TFROUND(16) TFROUND(24)
    x0 += KS2; x1 += KS0 + 2u;
    TFROUND(13) TFROUND(15) TFROUND(26) TFROUND(6)
    x0 += KS0; x1 += KS1 + 3u;
    TFROUND(17) TFROUND(29) TFROUND(16) TFROUND(24)
    x0 += KS1; x1 += KS2 + 4u;
    TFROUND(13) TFROUND(15) TFROUND(26) TFROUND(6)
    x0 += KS2; x1 += KS0 + 5u;
    return x0 ^ x1;
}

__device__ __forceinline__ float gumbel_from_bits(unsigned bits) {
    unsigned fb = (bits >> 9) | 0x3f800000u;
    float f = __uint_as_float(fb) - 1.0f;
    float u = fmaxf(f, 1.17549435082228751e-38f);
    return -logf(-logf(u));
}

// K1: resampling logits, transposed for coalesced access in the sampler.
__global__ void logits_kernel(const float* __restrict__ prob) {
    int tid = blockIdx.x * blockDim.x + threadIdx.x;  // tid = b*128 + p
    if (tid >= NB * NP) return;
    int b = tid >> 7;
    int p = tid & 127;
    float pr = prob[p * NB + b];
    d_LT[tid] = logf(0.5f * expf(pr) + 0.00390625f);  // (1-alpha)/P exact
}

// K2 (fused): 8 draws per 256-thread block. Each warp samples one (s,b) draw,
// then the whole block gathers the 8 particle rows (ALU phase of some blocks
// overlaps DRAM phase of others).
#define DRAWS_PER_BLK 8
__global__ __launch_bounds__(256) void sample_gather_kernel(
        const float* __restrict__ particles, float* __restrict__ out) {
    __shared__ int sh_idx[DRAWS_PER_BLK];

    int w    = threadIdx.x >> 5;                 // warp in block, 0..7
    int lane = threadIdx.x & 31;
    int r0   = blockIdx.x * DRAWS_PER_BLK;       // first draw id (= s*512 + b)
    int r    = r0 + w;                           // this warp's draw
    int s = r >> 9;
    int b = r & 511;

    const float* lt = d_LT + b * NP;
    unsigned base = (unsigned)r * 128u;          // s*65536 + b*128

    float best = -CUDART_INF_F;
    int bp = 0;
    #pragma unroll
    for (int j = 0; j < 4; j++) {
        int p = lane + 32 * j;
        unsigned bits = tf_bits(base + (unsigned)p);
        float v = gumbel_from_bits(bits) + lt[p];
        if (v > best) { best = v; bp = p; }      // p ascending -> first-max kept
    }
    #pragma unroll
    for (int off = 16; off > 0; off >>= 1) {
        float ov = __shfl_down_sync(0xffffffffu, best, off);
        int   op = __shfl_down_sync(0xffffffffu, bp, off);
        if (ov > best || (ov == best && op < bp)) { best = ov; bp = op; }
    }
    if (lane == 0) {
        sh_idx[w] = bp;
        d_idx[r] = bp;
    }
    __syncthreads();

    // Gather 8 rows x 512 floats = 1024 float4; 4 independent float4 per thread.
    // Writes: 16 KB contiguous per block (rows r0..r0+7 are consecutive).
    float4* dst = (float4*)(out + (size_t)r0 * NH);
    const float4* pf4 = (const float4*)particles;

    int j0 = threadIdx.x;                        // f4 index within block region
    int j1 = threadIdx.x + 256;
    int j2 = threadIdx.x + 512;
    int j3 = threadIdx.x + 768;
    // row k = j>>7 (128 f4 per row), col = j & 127
    size_t s0 = ((size_t)sh_idx[j0 >> 7] * NB + ((r0 + (j0 >> 7)) & 511)) * (NH/4) + (j0 & 127);
    size_t s1 = ((size_t)sh_idx[j1 >> 7] * NB + ((r0 + (j1 >> 7)) & 511)) * (NH/4) + (j1 & 127);
    size_t s2 = ((size_t)sh_idx[j2 >> 7] * NB + ((r0 + (j2 >> 7)) & 511)) * (NH/4) + (j2 & 127);
    size_t s3 = ((size_t)sh_idx[j3 >> 7] * NB + ((r0 + (j3 >> 7)) & 511)) * (NH/4) + (j3 & 127);
    float4 v0 = pf4[s0];
    float4 v1 = pf4[s1];
    float4 v2 = pf4[s2];
    float4 v3 = pf4[s3];
    dst[j0] = v0;
    dst[j1] = v1;
    dst[j2] = v2;
    dst[j3] = v3;
}

// K3: reweight + per-batch-column logsumexp. One block per b, 128 threads (= s).
__global__ void probnew_kernel(const float* __restrict__ prob, float* __restrict__ out_prob) {
    int b = blockIdx.x;
    int s = threadIdx.x;
    int idx = d_idx[s * NB + b];
    float pg = prob[idx * NB + b];
    float w = expf(pg);
    float w2 = w / (0.5f * w + 0.00390625f);
    float lw = logf(w2);

    __shared__ float sh[NP];
    sh[s] = lw;
    __syncthreads();
    #pragma unroll
    for (int off = 64; off > 0; off >>= 1) {
        if (s < off) sh[s] = fmaxf(sh[s], sh[s + off]);
        __syncthreads();
    }
    float m = sh[0];
    __syncthreads();
    sh[s] = expf(lw - m);
    __syncthreads();
    #pragma unroll
    for (int off = 64; off > 0; off >>= 1) {
        if (s < off) sh[s] += sh[s + off];
        __syncthreads();
    }
    float lse = m + logf(sh[0]);
    out_prob[s * NB + b] = lw - lse;
}

extern "C" void kernel_launch(void* const* d_in, const int* in_sizes, int n_in,
                              void* d_out, int out_size) {
    const float* particles = (const float*)d_in[0];   // [P*B, H]
    const float* prob      = (const float*)d_in[1];   // [P*B, 1]
    float* out = (float*)d_out;
    float* out_particles = out;                 // [P*B*H]
    float* out_prob = out + (size_t)PB * NH;    // [P*B]

    logits_kernel<<<(NB * NP + 255) / 256, 256>>>(prob);
    sample_gather_kernel<<<PB / DRAWS_PER_BLK, 256>>>(particles, out_particles);
    probnew_kernel<<<NB, NP>>>(prob, out_prob);
}

// round 4
// speedup vs baseline: 1.6986x; 1.0322x over previous
#include <cuda_runtime.h>
#include <math_constants.h>

#define NP 128           // particles
#define NB 512           // batch
#define NH 512           // hidden
#define PB (NP*NB)       // 65536

// threefry key from jax.random.key(42): (k0=0, k1=42)
#define KS0 0u
#define KS1 42u
#define KS2 (KS0 ^ KS1 ^ 0x1BD11BDAu)

__device__ float d_LT[NB * NP];   // LT[b*128 + p] = log(0.5*exp(prob[p,b]) + 0.5/128)
__device__ int   d_idx[PB];       // indices[s*512 + b]

#define TFROUND(r) { x0 += x1; x1 = __funnelshift_l(x1, x1, (r)); x1 ^= x0; }

// jax partitionable threefry: one block per element i, counter (hi=0, lo=i),
// 32-bit output = lane0 ^ lane1.  (bit-exact; do not modify)
__device__ __forceinline__ unsigned tf_bits(unsigned i) {
    unsigned x0 = KS0;        // counts_hi (=0) + ks0
    unsigned x1 = i + KS1;    // counts_lo + ks1
    TFROUND(13) TFROUND(15) TFROUND(26) TFROUND(6)
    x0 += KS1; x1 += KS2 + 1u;
    TFROUND(17) TFROUND(29) TFROUND(16) TFROUND(24)
    x0 += KS2; x1 += KS0 + 2u;
    TFROUND(13) TFROUND(15) TFROUND(26) TFROUND(6)
    x0 += KS0; x1 += KS1 + 3u;
    TFROUND(17) TFROUND(29) TFROUND(16) TFROUND(24)
    x0 += KS1; x1 += KS2 + 4u;
    TFROUND(13) TFROUND(15) TFROUND(26) TFROUND(6)
    x0 += KS2; x1 += KS0 + 5u;
    return x0 ^ x1;
}

__device__ __forceinline__ float gumbel_from_bits(unsigned bits) {
    unsigned fb = (bits >> 9) | 0x3f800000u;
    float f = __uint_as_float(fb) - 1.0f;
    float u = fmaxf(f, 1.17549435082228751e-38f);
    return -logf(-logf(u));
}

// K1: resampling logits, 32x32 smem-tiled transpose (coalesced both sides).
// grid (4, 16), block (32, 32).  d_LT[b*128+p] = log(0.5*exp(prob[p*512+b]) + 1/256)
__global__ __launch_bounds__(1024) void logits_kernel(const float* __restrict__ prob) {
    __shared__ float tile[32][33];
    int p0 = blockIdx.x * 32;
    int b0 = blockIdx.y * 32;
    int tx = threadIdx.x, ty = threadIdx.y;
    float pr = prob[(p0 + ty) * NB + (b0 + tx)];          // coalesced in tx
    tile[ty][tx] = logf(0.5f * expf(pr) + 0.00390625f);
    __syncthreads();
    d_LT[(b0 + ty) * NP + (p0 + tx)] = tile[tx][ty];      // coalesced in tx
}

// K2 (fused, barrier-free): one warp per draw r = s*512 + b.
// Warp samples via gumbel-argmax (butterfly reduce -> all lanes hold winner),
// then immediately gathers its 2KB particle row with 4 float4 per lane.
__global__ __launch_bounds__(256) void sample_gather_kernel(
        const float* __restrict__ particles, float* __restrict__ out) {
    int r    = (blockIdx.x * 256 + threadIdx.x) >> 5;    // draw id, 0..65535
    int lane = threadIdx.x & 31;
    int b = r & 511;

    const float* lt = d_LT + b * NP;
    unsigned base = (unsigned)r * 128u;                  // s*65536 + b*128

    float best = -CUDART_INF_F;
    int bp = 0;
    #pragma unroll
    for (int j = 0; j < 4; j++) {
        int p = lane + 32 * j;
        unsigned bits = tf_bits(base + (unsigned)p);
        float v = gumbel_from_bits(bits) + lt[p];
        if (v > best) { best = v; bp = p; }              // p ascending -> first-max kept
    }
    // butterfly argmax: symmetric comparator, tie -> lower p; all lanes converge
    #pragma unroll
    for (int off = 16; off > 0; off >>= 1) {
        float ov = __shfl_xor_sync(0xffffffffu, best, off);
        int   op = __shfl_xor_sync(0xffffffffu, bp, off);
        if (ov > best || (ov == best && op < bp)) { best = ov; bp = op; }
    }
    if (lane == 0) d_idx[r] = bp;

    // warp-local gather: src row = bp*512 + b, dst row = r. 4 independent f4/lane.
    const float4* src = (const float4*)particles + ((size_t)bp * NB + b) * (NH / 4);
    float4* dst = (float4*)out + (size_t)r * (NH / 4);
    float4 v0 = src[lane];
    float4 v1 = src[lane + 32];
    float4 v2 = src[lane + 64];
    float4 v3 = src[lane + 96];
    dst[lane]      = v0;
    dst[lane + 32] = v1;
    dst[lane + 64] = v2;
    dst[lane + 96] = v3;
}

// K3: reweight + per-batch-column logsumexp. One warp per b, 4 s-values per lane.
__global__ __launch_bounds__(256) void probnew_kernel(
        const float* __restrict__ prob, float* __restrict__ out_prob) {
    int b    = (blockIdx.x * 256 + threadIdx.x) >> 5;    // 0..511
    int lane = threadIdx.x & 31;

    float lw[4];
    float m = -CUDART_INF_F;
    #pragma unroll
    for (int k = 0; k < 4; k++) {
        int s = lane + 32 * k;
        int idx = d_idx[s * NB + b];
        float pg = prob[idx * NB + b];
        // match reference composition: w = exp(p); w = w/(a*w + c); lw = log(w)
        float w = expf(pg);
        float w2 = w / (0.5f * w + 0.00390625f);
        lw[k] = logf(w2);
        m = fmaxf(m, lw[k]);
    }
    #pragma unroll
    for (int off = 16; off > 0; off >>= 1)
        m = fmaxf(m, __shfl_xor_sync(0xffffffffu, m, off));

    float e = 0.0f;
    #pragma unroll
    for (int k = 0; k < 4; k++) e += expf(lw[k] - m);
    #pragma unroll
    for (int off = 16; off > 0; off >>= 1)
        e += __shfl_xor_sync(0xffffffffu, e, off);

    float lse = m + logf(e);
    #pragma unroll
    for (int k = 0; k < 4; k++)
        out_prob[(lane + 32 * k) * NB + b] = lw[k] - lse;
}

extern "C" void kernel_launch(void* const* d_in, const int* in_sizes, int n_in,
                              void* d_out, int out_size) {
    const float* particles = (const float*)d_in[0];   // [P*B, H]
    const float* prob      = (const float*)d_in[1];   // [P*B, 1]
    float* out = (float*)d_out;
    float* out_particles = out;                 // [P*B*H]
    float* out_prob = out + (size_t)PB * NH;    // [P*B]

    dim3 lgrid(NP / 32, NB / 32);
    dim3 lblk(32, 32);
    logits_kernel<<<lgrid, lblk>>>(prob);
    sample_gather_kernel<<<PB / 8, 256>>>(particles, out_particles);
    probnew_kernel<<<NB / 8, 256>>>(prob, out_prob);
}